// round 14
// baseline (speedup 1.0000x reference)
#include <cuda_runtime.h>
#include <math.h>

#define N_ROWS 100000
#define NF 50
#define NB 16
#define NK 15
#define FPC 1e-4
#define NCOL 25                   // 32-float words per row (800/32)
#define NSLICE 16                 // counter replication to cut atomic contention

// ---------------- device scratch (no allocation allowed) -------------------
__device__ unsigned g_comp[(size_t)N_ROWS * NCOL];   // 10 MB row-major mask words
__device__ unsigned g_tot[NSLICE][NF * NB];          // zero-init; fused wls re-zeroes
__device__ unsigned g_bad[NSLICE][NF * NB];
__device__ int      g_n1;                            // zero-init; rt resets
__device__ unsigned g_done;                          // completion ticket; last block resets
__device__ float    g_wuse[NF * NB];

// ---------------------------------------------------------------------------
__device__ __forceinline__ double red16(double v) {
    #pragma unroll
    for (int o = 8; o > 0; o >>= 1) v += __shfl_xor_sync(0xffffffffu, v, o);
    return v;
}

// Per-feature WLS (exact math of the standalone wls_kernel), run by one warp.
__device__ void wls_feature(int f, int lane, float* __restrict__ out) {
    const int n1 = g_n1;
    const int n0 = N_ROWS - n1;

    float woe_b = 0.f;
    double tot_b = 0.0;
    if (lane < NB) {
        unsigned ct = 0u, cb = 0u;
        #pragma unroll
        for (int s = 0; s < NSLICE; s++) {
            ct += g_tot[s][f * NB + lane];
            cb += g_bad[s][f * NB + lane];
            g_tot[s][f * NB + lane] = 0u;
            g_bad[s][f * NB + lane] = 0u;
        }
        int cg = (int)ct - (int)cb;
        woe_b = logf((float)cb / (float)n1 + (float)FPC)
              - logf((float)cg / (float)n0 + (float)FPC);
        tot_b = (double)ct / (double)N_ROWS;
    }

    const bool inK = (lane >= 1 && lane < NB);
    double s = red16(inK ? tot_b : 0.0);
    double pct = inK ? tot_b / s : 0.0;
    double w   = inK ? (double)woe_b : 0.0;

    unsigned nzmask = __ballot_sync(0xffffffffu, inK && pct != 0.0);
    int first = nzmask ? (__ffs(nzmask) - 2) : 0;

    double idxv = 0.0, ind = 0.0;
    if (inK) {
        double v = (double)(lane - first);
        idxv = v > 0.0 ? v : 0.0;
        ind  = (idxv != 0.0) ? 1.0 : 0.0;
    }
    double idx2 = idxv * idxv;

    double s00 = red16(pct * ind * ind);
    double s01 = red16(pct * ind * idxv);
    double s11 = red16(pct * idxv * idxv);
    double r0  = red16(pct * ind * w);
    double r1v = red16(pct * idxv * w);
    double det2 = s00 * s11 - s01 * s01;
    double c10 = (s11 * r0 - s01 * r1v) / det2;
    double c11 = (s00 * r1v - s01 * r0) / det2;
    double fit1 = ind * c10 + idxv * c11;

    double a00 = s00, a01 = s01, a11 = s11;
    double a02 = red16(pct * ind * idx2);
    double a12 = red16(pct * idxv * idx2);
    double a22 = red16(pct * idx2 * idx2);
    double b0 = r0, b1 = r1v;
    double b2 = red16(pct * idx2 * w);
    double m00 = a11 * a22 - a12 * a12;
    double m01 = a01 * a22 - a12 * a02;
    double m02 = a01 * a12 - a11 * a02;
    double det3 = a00 * m00 - a01 * m01 + a02 * m02;
    double c20 = (b0 * m00 - a01 * (b1 * a22 - a12 * b2) + a02 * (b1 * a12 - a11 * b2)) / det3;
    double c21 = (a00 * (b1 * a22 - a12 * b2) - b0 * m01 + a02 * (a01 * b2 - b1 * a02)) / det3;
    double c22 = (a00 * (a11 * b2 - b1 * a12) - a01 * (a01 * b2 - b1 * a02) + b0 * m02) / det3;
    double fit2 = ind * c20 + idxv * c21 + idx2 * c22;

    double mean = red16(w * pct);
    double d0 = w - mean;
    double d1 = fit1 - w;
    double d2 = fit2 - w;
    double sst  = red16(inK ? d0 * d0 * pct : 0.0);
    double sse1 = red16(inK ? d1 * d1 * pct : 0.0);
    double sse2 = red16(inK ? d2 * d2 * pct : 0.0);
    double r1 = 1.0 - sse1 / sst;
    double r2 = 1.0 - sse2 / sst;

    float* out_woe = out + (size_t)N_ROWS * NF;
    float* out_adj = out_woe + NF * NB;

    if (lane < NB) {
        out_woe[f * NB + lane] = woe_b;
        float a;
        if (lane == 0) a = woe_b;
        else a = (float)((fit1 * r1 + fit2 * r2) / (r1 + r2));
        out_adj[f * NB + lane] = a;
        g_wuse[f * NB + lane] = isnan(a) ? 0.0f : a;
    }
}

// ---------------------------------------------------------------------------
// Fused compress + count (EXACT R12 hot loop: 16-row tiles, byte-packed
// counters, 16-way striped flush) + last-block WLS tail (threadfence
// reduction pattern) — removes one kernel launch from the graph.
#define CC_ROWS 16
#define CC_BLOCK 256
#define CC_WPB (CC_BLOCK / 32)
#define CC_TILES (N_ROWS / CC_ROWS)                   // 6250
#define CC_BLOCKS ((CC_TILES + CC_WPB - 1) / CC_WPB)  // 782

__global__ void __launch_bounds__(CC_BLOCK)
compress_count_kernel(const float* __restrict__ x, const int* __restrict__ y,
                      float* __restrict__ out) {
    __shared__ bool s_last;
    const int tidb = threadIdx.x;
    const int lane = tidb & 31;
    const int tile = blockIdx.x * CC_WPB + (tidb >> 5);

    const int hi  = lane >> 4;      // which feature within the word
    const int bin = lane & 15;      // bin index

    if (tile < CC_TILES) {
        const int n0 = tile * CC_ROWS;

        unsigned tot[7], bad[7];
        #pragma unroll
        for (int j = 0; j < 7; j++) { tot[j] = 0u; bad[j] = 0u; }

        const int yv = (lane < CC_ROWS) ? y[n0 + lane] : 0;
        const unsigned ym = __ballot_sync(0xffffffffu, yv == 1);

        for (int r = 0; r < CC_ROWS; r++) {
            const float* row = x + (size_t)(n0 + r) * (NF * NB);
            const unsigned isbad = (ym >> r) & 1u;
            unsigned my = 0;
            #pragma unroll
            for (int i = 0; i < NCOL; i++) {
                float v = __ldcs(row + i * 32 + lane);
                unsigned b = __ballot_sync(0xffffffffu, v != 0.f);
                if (lane == i) my = b;
                unsigned bit = (b >> lane) & 1u;
                tot[i >> 2] += bit << ((i & 3) * 8);
                bad[i >> 2] += (bit & isbad) << ((i & 3) * 8);
            }
            if (lane < NCOL) g_comp[(size_t)(n0 + r) * NCOL + lane] = my;
        }

        unsigned* tslice = g_tot[tile & (NSLICE - 1)];
        unsigned* bslice = g_bad[tile & (NSLICE - 1)];
        #pragma unroll
        for (int j = 0; j < 7; j++) {
            #pragma unroll
            for (int q = 0; q < 4; q++) {
                int i = 4 * j + q;
                if (i < NCOL) {
                    int f = 2 * i + hi;
                    atomicAdd(&tslice[f * NB + bin], (tot[j] >> (8 * q)) & 0xFFu);
                    atomicAdd(&bslice[f * NB + bin], (bad[j] >> (8 * q)) & 0xFFu);
                }
            }
        }
        if (lane == 0) atomicAdd(&g_n1, __popc(ym));
    }

    // ---- completion ticket: last block runs the WLS tail ----
    __threadfence();
    __syncthreads();
    if (tidb == 0) s_last = (atomicAdd(&g_done, 1u) == CC_BLOCKS - 1);
    __syncthreads();

    if (s_last) {
        const int warp = tidb >> 5;
        for (int f = warp; f < NF; f += CC_WPB)
            wls_feature(f, lane, out);
        if (tidb == 0) g_done = 0u;
    }
}

// ---------------------------------------------------------------------------
// rt: EXACT R12 body/geometry (fixed-f-per-thread, 16-register LUT,
// 400 threads x 500 blocks), streamed mask loads. Also resets g_n1.
#define RT_THREADS 400
#define RT_ITERS 25
#define RT_BLOCKS (N_ROWS * NF / (RT_THREADS * RT_ITERS))   // 500

__global__ void __launch_bounds__(RT_THREADS)
rt_kernel(float* __restrict__ out) {
    if (blockIdx.x == 0 && threadIdx.x == 0) g_n1 = 0;

    const int tid = threadIdx.x;
    const int f = tid % NF;
    const size_t base = (size_t)blockIdx.x * (RT_THREADS * RT_ITERS);

    float wv[NB];
    #pragma unroll
    for (int b = 0; b < NB; b++) wv[b] = g_wuse[f * NB + b];

    const unsigned short* comp = (const unsigned short*)g_comp;

    #pragma unroll 5
    for (int i = 0; i < RT_ITERS; i++) {
        size_t p = base + (size_t)i * RT_THREADS + tid;
        unsigned m = __ldcs(comp + p);
        float s0 = 0.f, s1 = 0.f, s2 = 0.f, s3 = 0.f;
        #pragma unroll
        for (int b = 0; b < NB; b += 4) {
            s0 += ((m >> (b + 0)) & 1u) ? wv[b + 0] : 0.f;
            s1 += ((m >> (b + 1)) & 1u) ? wv[b + 1] : 0.f;
            s2 += ((m >> (b + 2)) & 1u) ? wv[b + 2] : 0.f;
            s3 += ((m >> (b + 3)) & 1u) ? wv[b + 3] : 0.f;
        }
        out[p] = (s0 + s1) + (s2 + s3);
    }
}

// ---------------------------------------------------------------------------
extern "C" void kernel_launch(void* const* d_in, const int* in_sizes, int n_in,
                              void* d_out, int out_size) {
    const float* x = (const float*)d_in[0];
    const int* y = (const int*)d_in[1];
    float* out = (float*)d_out;

    compress_count_kernel<<<CC_BLOCKS, CC_BLOCK>>>(x, y, out);

    rt_kernel<<<RT_BLOCKS, RT_THREADS>>>(out);
}

// round 15
// speedup vs baseline: 4.8868x; 4.8868x over previous
#include <cuda_runtime.h>
#include <math.h>

#define N_ROWS 100000
#define NF 50
#define NB 16
#define NK 15
#define FPC 1e-4
#define NCOL 25                   // 32-float words per row (800/32)
#define NSLICE 16                 // counter replication to cut atomic contention

// ---------------- device scratch (no allocation allowed) -------------------
__device__ unsigned g_comp[(size_t)N_ROWS * NCOL];   // 10 MB row-major mask words
__device__ unsigned g_tot[NSLICE][NF * NB];          // zero-init; wls sums + re-zeroes
__device__ unsigned g_bad[NSLICE][NF * NB];
__device__ int   g_n1;                               // zero-init; rt resets
__device__ float g_wuse[NF * NB];

// ---------------------------------------------------------------------------
// Fused compress + count: R6/R11 inner-loop structure, 16-row tiles
// (782 blocks) with byte-packed counters (4 words per u32; counts <= 16 fit
// in 8 bits) and 16-way striped flush. This exact build measured 61.1us at
// DRAM 67% / ALU 48.6% (co-saturated) — do not restructure.
#define CC_ROWS 16
#define CC_BLOCK 256
#define CC_WPB (CC_BLOCK / 32)
#define CC_TILES (N_ROWS / CC_ROWS)                   // 6250
#define CC_BLOCKS ((CC_TILES + CC_WPB - 1) / CC_WPB)  // 782

__global__ void __launch_bounds__(CC_BLOCK)
compress_count_kernel(const float* __restrict__ x, const int* __restrict__ y) {
    const int lane = threadIdx.x & 31;
    const int tile = blockIdx.x * CC_WPB + (threadIdx.x >> 5);
    if (tile >= CC_TILES) return;
    const int n0 = tile * CC_ROWS;

    const int hi  = lane >> 4;      // which feature within the word
    const int bin = lane & 15;      // bin index

    unsigned tot[7], bad[7];
    #pragma unroll
    for (int j = 0; j < 7; j++) { tot[j] = 0u; bad[j] = 0u; }

    const int yv = (lane < CC_ROWS) ? y[n0 + lane] : 0;
    const unsigned ym = __ballot_sync(0xffffffffu, yv == 1);

    for (int r = 0; r < CC_ROWS; r++) {
        const float* row = x + (size_t)(n0 + r) * (NF * NB);
        const unsigned isbad = (ym >> r) & 1u;
        unsigned my = 0;
        #pragma unroll
        for (int i = 0; i < NCOL; i++) {
            float v = __ldcs(row + i * 32 + lane);
            unsigned b = __ballot_sync(0xffffffffu, v != 0.f);
            if (lane == i) my = b;
            unsigned bit = (b >> lane) & 1u;
            tot[i >> 2] += bit << ((i & 3) * 8);
            bad[i >> 2] += (bit & isbad) << ((i & 3) * 8);
        }
        if (lane < NCOL) g_comp[(size_t)(n0 + r) * NCOL + lane] = my;
    }

    // flush: fixed (f,bin) per (word, lane) -> spread atomics, striped slice
    unsigned* tslice = g_tot[tile & (NSLICE - 1)];
    unsigned* bslice = g_bad[tile & (NSLICE - 1)];
    #pragma unroll
    for (int j = 0; j < 7; j++) {
        #pragma unroll
        for (int q = 0; q < 4; q++) {
            int i = 4 * j + q;
            if (i < NCOL) {
                int f = 2 * i + hi;
                atomicAdd(&tslice[f * NB + bin], (tot[j] >> (8 * q)) & 0xFFu);
                atomicAdd(&bslice[f * NB + bin], (bad[j] >> (8 * q)) & 0xFFu);
            }
        }
    }
    if (lane == 0) atomicAdd(&g_n1, __popc(ym));
}

// ---------------------------------------------------------------------------
// WLS — one warp per feature; shfl-butterfly reductions; solves on all lanes.
// Sums the counter slices and re-zeroes them (replay-clean).
__device__ __forceinline__ double red16(double v) {
    #pragma unroll
    for (int o = 8; o > 0; o >>= 1) v += __shfl_xor_sync(0xffffffffu, v, o);
    return v;
}

__global__ void wls_kernel(float* __restrict__ out) {
    const int f = blockIdx.x;
    const int lane = threadIdx.x;

    const int n1 = g_n1;
    const int n0 = N_ROWS - n1;

    float woe_b = 0.f;
    double tot_b = 0.0;
    if (lane < NB) {
        unsigned ct = 0u, cb = 0u;
        #pragma unroll
        for (int s = 0; s < NSLICE; s++) {
            ct += g_tot[s][f * NB + lane];
            cb += g_bad[s][f * NB + lane];
            g_tot[s][f * NB + lane] = 0u;
            g_bad[s][f * NB + lane] = 0u;
        }
        int cg = (int)ct - (int)cb;
        woe_b = logf((float)cb / (float)n1 + (float)FPC)
              - logf((float)cg / (float)n0 + (float)FPC);
        tot_b = (double)ct / (double)N_ROWS;
    }

    const bool inK = (lane >= 1 && lane < NB);
    double s = red16(inK ? tot_b : 0.0);
    double pct = inK ? tot_b / s : 0.0;
    double w   = inK ? (double)woe_b : 0.0;

    unsigned nzmask = __ballot_sync(0xffffffffu, inK && pct != 0.0);
    int first = nzmask ? (__ffs(nzmask) - 2) : 0;

    double idxv = 0.0, ind = 0.0;
    if (inK) {
        double v = (double)(lane - first);
        idxv = v > 0.0 ? v : 0.0;
        ind  = (idxv != 0.0) ? 1.0 : 0.0;
    }
    double idx2 = idxv * idxv;

    double s00 = red16(pct * ind * ind);
    double s01 = red16(pct * ind * idxv);
    double s11 = red16(pct * idxv * idxv);
    double r0  = red16(pct * ind * w);
    double r1v = red16(pct * idxv * w);
    double det2 = s00 * s11 - s01 * s01;
    double c10 = (s11 * r0 - s01 * r1v) / det2;
    double c11 = (s00 * r1v - s01 * r0) / det2;
    double fit1 = ind * c10 + idxv * c11;

    double a00 = s00, a01 = s01, a11 = s11;
    double a02 = red16(pct * ind * idx2);
    double a12 = red16(pct * idxv * idx2);
    double a22 = red16(pct * idx2 * idx2);
    double b0 = r0, b1 = r1v;
    double b2 = red16(pct * idx2 * w);
    double m00 = a11 * a22 - a12 * a12;
    double m01 = a01 * a22 - a12 * a02;
    double m02 = a01 * a12 - a11 * a02;
    double det3 = a00 * m00 - a01 * m01 + a02 * m02;
    double c20 = (b0 * m00 - a01 * (b1 * a22 - a12 * b2) + a02 * (b1 * a12 - a11 * b2)) / det3;
    double c21 = (a00 * (b1 * a22 - a12 * b2) - b0 * m01 + a02 * (a01 * b2 - b1 * a02)) / det3;
    double c22 = (a00 * (a11 * b2 - b1 * a12) - a01 * (a01 * b2 - b1 * a02) + b0 * m02) / det3;
    double fit2 = ind * c20 + idxv * c21 + idx2 * c22;

    double mean = red16(w * pct);
    double d0 = w - mean;
    double d1 = fit1 - w;
    double d2 = fit2 - w;
    double sst  = red16(inK ? d0 * d0 * pct : 0.0);
    double sse1 = red16(inK ? d1 * d1 * pct : 0.0);
    double sse2 = red16(inK ? d2 * d2 * pct : 0.0);
    double r1 = 1.0 - sse1 / sst;
    double r2 = 1.0 - sse2 / sst;

    float* out_woe = out + (size_t)N_ROWS * NF;
    float* out_adj = out_woe + NF * NB;

    if (lane < NB) {
        out_woe[f * NB + lane] = woe_b;
        float a;
        if (lane == 0) a = woe_b;
        else a = (float)((fit1 * r1 + fit2 * r2) / (r1 + r2));
        out_adj[f * NB + lane] = a;
        g_wuse[f * NB + lane] = isnan(a) ? 0.0f : a;
    }
}

// ---------------------------------------------------------------------------
// rt: R3 loop body, 400 threads x 500 blocks geometry (R12 build).
// Also resets g_n1 for the next replay.
#define RT_THREADS 400
#define RT_ITERS 25
#define RT_BLOCKS (N_ROWS * NF / (RT_THREADS * RT_ITERS))   // 500

__global__ void __launch_bounds__(RT_THREADS)
rt_kernel(float* __restrict__ out) {
    if (blockIdx.x == 0 && threadIdx.x == 0) g_n1 = 0;

    const int tid = threadIdx.x;
    const int f = tid % NF;
    const size_t base = (size_t)blockIdx.x * (RT_THREADS * RT_ITERS);

    float wv[NB];
    #pragma unroll
    for (int b = 0; b < NB; b++) wv[b] = g_wuse[f * NB + b];

    const unsigned short* comp = (const unsigned short*)g_comp;

    #pragma unroll 5
    for (int i = 0; i < RT_ITERS; i++) {
        size_t p = base + (size_t)i * RT_THREADS + tid;
        unsigned m = comp[p];
        float s0 = 0.f, s1 = 0.f, s2 = 0.f, s3 = 0.f;
        #pragma unroll
        for (int b = 0; b < NB; b += 4) {
            s0 += ((m >> (b + 0)) & 1u) ? wv[b + 0] : 0.f;
            s1 += ((m >> (b + 1)) & 1u) ? wv[b + 1] : 0.f;
            s2 += ((m >> (b + 2)) & 1u) ? wv[b + 2] : 0.f;
            s3 += ((m >> (b + 3)) & 1u) ? wv[b + 3] : 0.f;
        }
        out[p] = (s0 + s1) + (s2 + s3);
    }
}

// ---------------------------------------------------------------------------
extern "C" void kernel_launch(void* const* d_in, const int* in_sizes, int n_in,
                              void* d_out, int out_size) {
    const float* x = (const float*)d_in[0];
    const int* y = (const int*)d_in[1];
    float* out = (float*)d_out;

    compress_count_kernel<<<CC_BLOCKS, CC_BLOCK>>>(x, y);

    wls_kernel<<<NF, 32>>>(out);

    rt_kernel<<<RT_BLOCKS, RT_THREADS>>>(out);
}

// round 16
// speedup vs baseline: 4.9828x; 1.0196x over previous
#include <cuda_runtime.h>
#include <math.h>

#define N_ROWS 100000
#define NF 50
#define NB 16
#define NK 15
#define FPC 1e-4
#define NCOL 25                   // 32-float words per row (800/32)
#define NSLICE 16                 // counter replication to cut atomic contention
#define LUT_STRIDE 65             // 64 entries + 1 pad (bank skew)
#define LUT_SIZE (NF * LUT_STRIDE)

// ---------------- device scratch (no allocation allowed) -------------------
__device__ unsigned g_comp[(size_t)N_ROWS * NCOL];   // 10 MB row-major mask words
__device__ unsigned g_tot[NSLICE][NF * NB];          // zero-init; wls sums + re-zeroes
__device__ unsigned g_bad[NSLICE][NF * NB];
__device__ int   g_n1;                               // zero-init; rt resets
__device__ float g_lut[LUT_SIZE];                    // nibble-sum LUT, built by wls

// ---------------------------------------------------------------------------
// Fused compress + count: R12 build, measured 61.1us at DRAM 67% / ALU 49%
// (co-saturated). PROTECTED — do not restructure.
#define CC_ROWS 16
#define CC_BLOCK 256
#define CC_WPB (CC_BLOCK / 32)
#define CC_TILES (N_ROWS / CC_ROWS)                   // 6250
#define CC_BLOCKS ((CC_TILES + CC_WPB - 1) / CC_WPB)  // 782

__global__ void __launch_bounds__(CC_BLOCK)
compress_count_kernel(const float* __restrict__ x, const int* __restrict__ y) {
    const int lane = threadIdx.x & 31;
    const int tile = blockIdx.x * CC_WPB + (threadIdx.x >> 5);
    if (tile >= CC_TILES) return;
    const int n0 = tile * CC_ROWS;

    const int hi  = lane >> 4;      // which feature within the word
    const int bin = lane & 15;      // bin index

    unsigned tot[7], bad[7];
    #pragma unroll
    for (int j = 0; j < 7; j++) { tot[j] = 0u; bad[j] = 0u; }

    const int yv = (lane < CC_ROWS) ? y[n0 + lane] : 0;
    const unsigned ym = __ballot_sync(0xffffffffu, yv == 1);

    for (int r = 0; r < CC_ROWS; r++) {
        const float* row = x + (size_t)(n0 + r) * (NF * NB);
        const unsigned isbad = (ym >> r) & 1u;
        unsigned my = 0;
        #pragma unroll
        for (int i = 0; i < NCOL; i++) {
            float v = __ldcs(row + i * 32 + lane);
            unsigned b = __ballot_sync(0xffffffffu, v != 0.f);
            if (lane == i) my = b;
            unsigned bit = (b >> lane) & 1u;
            tot[i >> 2] += bit << ((i & 3) * 8);
            bad[i >> 2] += (bit & isbad) << ((i & 3) * 8);
        }
        if (lane < NCOL) g_comp[(size_t)(n0 + r) * NCOL + lane] = my;
    }

    // flush: fixed (f,bin) per (word, lane) -> spread atomics, striped slice
    unsigned* tslice = g_tot[tile & (NSLICE - 1)];
    unsigned* bslice = g_bad[tile & (NSLICE - 1)];
    #pragma unroll
    for (int j = 0; j < 7; j++) {
        #pragma unroll
        for (int q = 0; q < 4; q++) {
            int i = 4 * j + q;
            if (i < NCOL) {
                int f = 2 * i + hi;
                atomicAdd(&tslice[f * NB + bin], (tot[j] >> (8 * q)) & 0xFFu);
                atomicAdd(&bslice[f * NB + bin], (bad[j] >> (8 * q)) & 0xFFu);
            }
        }
    }
    if (lane == 0) atomicAdd(&g_n1, __popc(ym));
}

// ---------------------------------------------------------------------------
// WLS — one warp per feature; shfl-butterfly reductions; solves on all lanes.
// Sums the counter slices and re-zeroes them (replay-clean). Additionally
// builds the 64-entry nibble-sum LUT for this feature into g_lut.
__device__ __forceinline__ double red16(double v) {
    #pragma unroll
    for (int o = 8; o > 0; o >>= 1) v += __shfl_xor_sync(0xffffffffu, v, o);
    return v;
}

__global__ void wls_kernel(float* __restrict__ out) {
    const int f = blockIdx.x;
    const int lane = threadIdx.x;

    const int n1 = g_n1;
    const int n0 = N_ROWS - n1;

    float woe_b = 0.f;
    double tot_b = 0.0;
    if (lane < NB) {
        unsigned ct = 0u, cb = 0u;
        #pragma unroll
        for (int s = 0; s < NSLICE; s++) {
            ct += g_tot[s][f * NB + lane];
            cb += g_bad[s][f * NB + lane];
            g_tot[s][f * NB + lane] = 0u;
            g_bad[s][f * NB + lane] = 0u;
        }
        int cg = (int)ct - (int)cb;
        woe_b = logf((float)cb / (float)n1 + (float)FPC)
              - logf((float)cg / (float)n0 + (float)FPC);
        tot_b = (double)ct / (double)N_ROWS;
    }

    const bool inK = (lane >= 1 && lane < NB);
    double s = red16(inK ? tot_b : 0.0);
    double pct = inK ? tot_b / s : 0.0;
    double w   = inK ? (double)woe_b : 0.0;

    unsigned nzmask = __ballot_sync(0xffffffffu, inK && pct != 0.0);
    int first = nzmask ? (__ffs(nzmask) - 2) : 0;

    double idxv = 0.0, ind = 0.0;
    if (inK) {
        double v = (double)(lane - first);
        idxv = v > 0.0 ? v : 0.0;
        ind  = (idxv != 0.0) ? 1.0 : 0.0;
    }
    double idx2 = idxv * idxv;

    double s00 = red16(pct * ind * ind);
    double s01 = red16(pct * ind * idxv);
    double s11 = red16(pct * idxv * idxv);
    double r0  = red16(pct * ind * w);
    double r1v = red16(pct * idxv * w);
    double det2 = s00 * s11 - s01 * s01;
    double c10 = (s11 * r0 - s01 * r1v) / det2;
    double c11 = (s00 * r1v - s01 * r0) / det2;
    double fit1 = ind * c10 + idxv * c11;

    double a00 = s00, a01 = s01, a11 = s11;
    double a02 = red16(pct * ind * idx2);
    double a12 = red16(pct * idxv * idx2);
    double a22 = red16(pct * idx2 * idx2);
    double b0 = r0, b1 = r1v;
    double b2 = red16(pct * idx2 * w);
    double m00 = a11 * a22 - a12 * a12;
    double m01 = a01 * a22 - a12 * a02;
    double m02 = a01 * a12 - a11 * a02;
    double det3 = a00 * m00 - a01 * m01 + a02 * m02;
    double c20 = (b0 * m00 - a01 * (b1 * a22 - a12 * b2) + a02 * (b1 * a12 - a11 * b2)) / det3;
    double c21 = (a00 * (b1 * a22 - a12 * b2) - b0 * m01 + a02 * (a01 * b2 - b1 * a02)) / det3;
    double c22 = (a00 * (a11 * b2 - b1 * a12) - a01 * (a01 * b2 - b1 * a02) + b0 * m02) / det3;
    double fit2 = ind * c20 + idxv * c21 + idx2 * c22;

    double mean = red16(w * pct);
    double d0 = w - mean;
    double d1 = fit1 - w;
    double d2 = fit2 - w;
    double sst  = red16(inK ? d0 * d0 * pct : 0.0);
    double sse1 = red16(inK ? d1 * d1 * pct : 0.0);
    double sse2 = red16(inK ? d2 * d2 * pct : 0.0);
    double r1 = 1.0 - sse1 / sst;
    double r2 = 1.0 - sse2 / sst;

    float* out_woe = out + (size_t)N_ROWS * NF;
    float* out_adj = out_woe + NF * NB;

    float af = 0.f;                 // w_use value for this lane's bin (0 if lane>=16)
    if (lane < NB) {
        out_woe[f * NB + lane] = woe_b;
        float a;
        if (lane == 0) a = woe_b;
        else a = (float)((fit1 * r1 + fit2 * r2) / (r1 + r2));
        out_adj[f * NB + lane] = a;
        af = isnan(a) ? 0.0f : a;
    }

    // Build the nibble-sum LUT: entry (pos, nib) = sum of w_use[f][pos*4+k]
    // over set bits k of nib. 2 entries per lane; sources via shfl.
    #pragma unroll
    for (int e = lane; e < 64; e += 32) {
        int pos = e >> 4;
        int nib = e & 15;
        float v = 0.f;
        #pragma unroll
        for (int k = 0; k < 4; k++) {
            float wk = __shfl_sync(0xffffffffu, af, pos * 4 + k);
            if ((nib >> k) & 1) v += wk;
        }
        g_lut[f * LUT_STRIDE + e] = v;
    }
}

// ---------------------------------------------------------------------------
// rt via smem nibble LUT: one u32 load = 2 masks (features 2c, 2c+1 fixed per
// thread since 800 % 25 == 0); 8 LDS + 6 FADD per 2 outputs; float2 stores.
// LUT copied (not computed) from g_lut. Also resets g_n1 for the next replay.
#define RT_THREADS 800
#define RT_ITERS 5
#define RT_BLOCKS 625            // 625 * 800 * 5 = 2,500,000 u32 words

__global__ void __launch_bounds__(RT_THREADS)
rt_kernel(float* __restrict__ out) {
    __shared__ float s_lut[LUT_SIZE];

    if (blockIdx.x == 0 && threadIdx.x == 0) g_n1 = 0;

    const int tid = threadIdx.x;
    for (int e = tid; e < LUT_SIZE; e += RT_THREADS) s_lut[e] = g_lut[e];
    __syncthreads();

    const int c = tid % 25;
    const int fb0 = (2 * c) * LUT_STRIDE;
    const int fb1 = fb0 + LUT_STRIDE;
    const unsigned base = (unsigned)blockIdx.x * (RT_THREADS * RT_ITERS);
    float2* out2 = (float2*)out;

    #pragma unroll
    for (int i = 0; i < RT_ITERS; i++) {
        unsigned q = base + (unsigned)i * RT_THREADS + tid;
        unsigned m = g_comp[q];
        float r0 = s_lut[fb0 +      (m        & 15u)]
                 + s_lut[fb0 + 16 + ((m >> 4)  & 15u)]
                 + s_lut[fb0 + 32 + ((m >> 8)  & 15u)]
                 + s_lut[fb0 + 48 + ((m >> 12) & 15u)];
        float r1 = s_lut[fb1 +      ((m >> 16) & 15u)]
                 + s_lut[fb1 + 16 + ((m >> 20) & 15u)]
                 + s_lut[fb1 + 32 + ((m >> 24) & 15u)]
                 + s_lut[fb1 + 48 + ( m >> 28       )];
        float2 rv;
        rv.x = r0;
        rv.y = r1;
        out2[q] = rv;
    }
}

// ---------------------------------------------------------------------------
extern "C" void kernel_launch(void* const* d_in, const int* in_sizes, int n_in,
                              void* d_out, int out_size) {
    const float* x = (const float*)d_in[0];
    const int* y = (const int*)d_in[1];
    float* out = (float*)d_out;

    compress_count_kernel<<<CC_BLOCKS, CC_BLOCK>>>(x, y);

    wls_kernel<<<NF, 32>>>(out);

    rt_kernel<<<RT_BLOCKS, RT_THREADS>>>(out);
}